// round 3
// baseline (speedup 1.0000x reference)
#include <cuda_runtime.h>

// CrossAttention collapses: K/V are one vector broadcast over T keys, so
// softmax over identical logits is uniform and y == v for every query.
// out[b,t,:] = ((vf[b] @ Wv + bv) @ Wp + bp)  broadcast over t.
//
// Inputs (metadata order): x[0], visual_features[1], Wq[2], bq[3], Wk[4],
// bk[5], Wv[6], bv[7], Wp[8], bp[9].  x/Wq/bq/Wk/bk are mathematically dead.

#define CDIM 1024
#define BDIM 4
#define TDIM 1024

__device__ float g_vv[BDIM * CDIM];  // vf @ Wv + bv
__device__ float g_r [BDIM * CDIM];  // (vf @ Wv + bv) @ Wp + bp

// out[b, j] = bias[j] + sum_i in[b, i] * W[i, j]
// Grid: (CDIM/128, BDIM), 128 threads. W reads coalesced across j-threads;
// the 4KB input row is staged in shared once per block.
__global__ __launch_bounds__(128) void proj_kernel(
    const float* __restrict__ in, const float* __restrict__ W,
    const float* __restrict__ bias, float* __restrict__ out)
{
    __shared__ float sh_in[CDIM];
    const int b = blockIdx.y;
    const int j = blockIdx.x * 128 + threadIdx.x;

    // Stage the input row (1024 floats) cooperatively.
    const float* row = in + b * CDIM;
    #pragma unroll
    for (int k = 0; k < CDIM / 128; ++k)
        sh_in[threadIdx.x + k * 128] = row[threadIdx.x + k * 128];
    __syncthreads();

    float acc = bias[j];
    #pragma unroll 8
    for (int i = 0; i < CDIM; ++i)
        acc += sh_in[i] * __ldg(&W[i * CDIM + j]);

    out[b * CDIM + j] = acc;
}

// out[b, t, c] = g_r[b, c] — 16 MB of float4 stores, fully spread over SMs.
__global__ __launch_bounds__(256) void bcast_kernel(float4* __restrict__ out)
{
    const int idx = blockIdx.x * 256 + threadIdx.x;   // 0 .. B*T*C/4-1
    const int c4  = idx & (CDIM / 4 - 1);             // column / 4
    const int b   = idx >> 18;                        // T*C/4 = 2^18
    const float4* __restrict__ r4 = reinterpret_cast<const float4*>(g_r);
    out[idx] = __ldg(&r4[b * (CDIM / 4) + c4]);
}

extern "C" void kernel_launch(void* const* d_in, const int* in_sizes, int n_in,
                              void* d_out, int out_size)
{
    (void)in_sizes; (void)n_in; (void)out_size;
    const float* vf = (const float*)d_in[1];
    const float* Wv = (const float*)d_in[6];
    const float* bv = (const float*)d_in[7];
    const float* Wp = (const float*)d_in[8];
    const float* bp = (const float*)d_in[9];
    float* out = (float*)d_out;

    float *vv_ptr = nullptr, *r_ptr = nullptr;
    cudaGetSymbolAddress((void**)&vv_ptr, g_vv);  // host-side query, capture-safe
    cudaGetSymbolAddress((void**)&r_ptr,  g_r);

    dim3 pgrid(CDIM / 128, BDIM);
    proj_kernel<<<pgrid, 128>>>(vf,     Wv, bv, vv_ptr);  // vv = vf @ Wv + bv
    proj_kernel<<<pgrid, 128>>>(vv_ptr, Wp, bp, r_ptr);   // r  = vv @ Wp + bp

    const int n4 = BDIM * TDIM * CDIM / 4;                // 1,048,576 float4
    bcast_kernel<<<n4 / 256, 256>>>((float4*)out);
}

// round 4
// speedup vs baseline: 4.1037x; 4.1037x over previous
#include <cuda_runtime.h>

// CrossAttention collapses: K/V are one visual_features vector broadcast over
// all T keys, softmax over identical logits is uniform, so y == v everywhere:
//   out[b,t,:] = ((vf[b] @ Wv + bv) @ Wp + bp)   broadcast over t.
// x / Wq / bq / Wk / bk are mathematically dead.
//
// R3 change: the projections were latency-bound (32 blocks, 0.8% DRAM).
// Split-K across 32 chunks -> 256 blocks, float4 weight loads, MLP~32.

#define CDIM  1024
#define BDIM  4
#define TDIM  1024
#define KS    32              // split-K chunk count
#define ROWS  (CDIM / KS)     // 32 reduction rows per chunk
#define JT    128             // threads per proj block
#define JSPAN (JT * 4)        // 512 output columns per block (float4/thread)
#define JBLK  (CDIM / JSPAN)  // 2

__device__ float g_pvv[KS][BDIM][CDIM];  // partials of vf @ Wv
__device__ float g_pr [KS][BDIM][CDIM];  // partials of vv @ Wp
__device__ float g_r  [BDIM][CDIM];      // final row to broadcast

// ---------------------------------------------------------------------------
// L1: partial[k][b][j0..j0+3] = sum_{i in chunk k} vf[b,i] * Wv[i,j]
// grid (JBLK, BDIM, KS), block JT. W reads: 2KB contiguous per row per block.
__global__ __launch_bounds__(JT) void vv_partial_kernel(
    const float* __restrict__ vf, const float* __restrict__ Wv)
{
    const int jx = blockIdx.x, b = blockIdx.y, k = blockIdx.z;
    const int j0 = jx * JSPAN + threadIdx.x * 4;

    __shared__ float s_in[ROWS];
    if (threadIdx.x < ROWS)
        s_in[threadIdx.x] = vf[b * CDIM + k * ROWS + threadIdx.x];
    __syncthreads();

    float4 acc = make_float4(0.f, 0.f, 0.f, 0.f);
    #pragma unroll
    for (int i = 0; i < ROWS; ++i) {
        const float4 w = __ldg((const float4*)&Wv[(k * ROWS + i) * CDIM + j0]);
        const float s = s_in[i];
        acc.x += s * w.x; acc.y += s * w.y; acc.z += s * w.z; acc.w += s * w.w;
    }
    *(float4*)&g_pvv[k][b][j0] = acc;
}

// ---------------------------------------------------------------------------
// L2: reduce the vv slice this block needs (32 values x 32 partials + bv)
// in shared, then compute partials of vv @ Wp. grid (JBLK, BDIM, KS), block JT.
__global__ __launch_bounds__(JT) void r_partial_kernel(
    const float* __restrict__ bv, const float* __restrict__ Wp)
{
    const int jx = blockIdx.x, b = blockIdx.y, k = blockIdx.z;
    const int j0 = jx * JSPAN + threadIdx.x * 4;

    __shared__ float s_red[4][ROWS];
    __shared__ float s_in[ROWS];

    // 128 threads: lane i (0..31) x partial-group kg (0..3, 8 partials each)
    {
        const int i  = threadIdx.x & 31;
        const int kg = threadIdx.x >> 5;
        float s = 0.f;
        #pragma unroll
        for (int kk = kg * 8; kk < kg * 8 + 8; ++kk)
            s += g_pvv[kk][b][k * ROWS + i];
        s_red[kg][i] = s;
    }
    __syncthreads();
    if (threadIdx.x < ROWS)
        s_in[threadIdx.x] = s_red[0][threadIdx.x] + s_red[1][threadIdx.x]
                          + s_red[2][threadIdx.x] + s_red[3][threadIdx.x]
                          + bv[k * ROWS + threadIdx.x];
    __syncthreads();

    float4 acc = make_float4(0.f, 0.f, 0.f, 0.f);
    #pragma unroll
    for (int i = 0; i < ROWS; ++i) {
        const float4 w = __ldg((const float4*)&Wp[(k * ROWS + i) * CDIM + j0]);
        const float s = s_in[i];
        acc.x += s * w.x; acc.y += s * w.y; acc.z += s * w.z; acc.w += s * w.w;
    }
    *(float4*)&g_pr[k][b][j0] = acc;
}

// ---------------------------------------------------------------------------
// L3: g_r[b][j] = bp[j] + sum_k g_pr[k][b][j]. 4096 outputs, trivial.
__global__ __launch_bounds__(512) void r_reduce_kernel(const float* __restrict__ bp)
{
    const int idx = blockIdx.x * 512 + threadIdx.x;   // 0..4095
    const int b = idx >> 10;
    const int j = idx & (CDIM - 1);
    float s = bp[j];
    #pragma unroll
    for (int k = 0; k < KS; ++k)
        s += g_pr[k][b][j];
    g_r[b][j] = s;
}

// ---------------------------------------------------------------------------
// L4: out[b,t,:] = g_r[b,:] — 16 MB of coalesced float4 stores.
__global__ __launch_bounds__(256) void bcast_kernel(float4* __restrict__ out)
{
    const int idx = blockIdx.x * 256 + threadIdx.x;   // 0 .. B*T*C/4-1
    const int c4  = idx & (CDIM / 4 - 1);
    const int b   = idx >> 18;                        // T*C/4 = 2^18
    const float4* __restrict__ r4 = reinterpret_cast<const float4*>(g_r);
    out[idx] = __ldg(&r4[b * (CDIM / 4) + c4]);
}

extern "C" void kernel_launch(void* const* d_in, const int* in_sizes, int n_in,
                              void* d_out, int out_size)
{
    (void)in_sizes; (void)n_in; (void)out_size;
    const float* vf = (const float*)d_in[1];
    const float* Wv = (const float*)d_in[6];
    const float* bv = (const float*)d_in[7];
    const float* Wp = (const float*)d_in[8];
    const float* bp = (const float*)d_in[9];

    dim3 pgrid(JBLK, BDIM, KS);                       // 2 x 4 x 32 = 256 blocks
    vv_partial_kernel<<<pgrid, JT>>>(vf, Wv);
    r_partial_kernel <<<pgrid, JT>>>(bv, Wp);
    r_reduce_kernel  <<<BDIM * CDIM / 512, 512>>>(bp);

    const int n4 = BDIM * TDIM * CDIM / 4;            // 1,048,576 float4
    bcast_kernel<<<n4 / 256, 256>>>((float4*)d_out);
}